// round 4
// baseline (speedup 1.0000x reference)
#include <cuda_runtime.h>

#define EPSF 1e-8f
constexpr int B  = 8;
constexpr int Nn = 2048;
constexpr int H  = 128;
constexpr int TM = 64;          // fm/apply row tile
constexpr int LD = 132;         // padded smem leading dim (floats)
constexpr int SPL = 16;         // split-K factor for C = N^T H
constexpr int RC  = Nn / SPL;   // 128 rows per cmat block (2 smem stages of 64)

// Scratch (device globals: allocation-free rule)
__device__ float g_n1[B * Nn * H];
__device__ float g_n2[B * Nn * H];
__device__ float g_agg1[B * Nn * H];
__device__ float g_agg2[B * Nn * H];
__device__ float g_part[2 * B * SPL * H * H];
__device__ float g_C[2 * B * H * H];

// ---- packed fp32 helpers (Blackwell FFMA2 path) ------------------------------
__device__ __forceinline__ unsigned long long bcast2(float x) {
    unsigned long long r;
    asm("mov.b64 %0, {%1, %1};" : "=l"(r) : "f"(x));
    return r;
}
__device__ __forceinline__ void ffma2(unsigned long long& d,
                                      unsigned long long a, unsigned long long b) {
    asm("fma.rn.f32x2 %0, %1, %2, %0;" : "+l"(d) : "l"(a), "l"(b));
}
__device__ __forceinline__ float2 lohi(unsigned long long v) {
    float2 r;
    asm("mov.b64 {%0, %1}, %2;" : "=f"(r.x), "=f"(r.y) : "l"(v));
    return r;
}

// ---------------------------------------------------------------------------
// K1: row-normalize h1 -> g_n1, h2 -> g_n2. One warp per row (H=128).
// ---------------------------------------------------------------------------
__global__ void normalize_kernel(const float* __restrict__ h1,
                                 const float* __restrict__ h2) {
    int warp = (blockIdx.x * blockDim.x + threadIdx.x) >> 5;
    int lane = threadIdx.x & 31;
    const float* src;
    float* dst;
    int row;
    if (warp < B * Nn) { src = h1; dst = g_n1; row = warp; }
    else               { src = h2; dst = g_n2; row = warp - B * Nn; }

    float4 v = ((const float4*)(src + (size_t)row * H))[lane];
    float ss = v.x * v.x + v.y * v.y + v.z * v.z + v.w * v.w;
#pragma unroll
    for (int o = 16; o; o >>= 1) ss += __shfl_xor_sync(0xffffffffu, ss, o);
    float inv = 1.0f / fmaxf(sqrtf(ss), EPSF);
    ((float4*)(dst + (size_t)row * H))[lane] =
        make_float4(v.x * inv, v.y * inv, v.z * inv, v.w * inv);
}

// ---------------------------------------------------------------------------
// K2a: split-K partials of C = N^T H  [128x128] per (b, which, split).
// Packed: i-pairs of N natural from 16B loads; H broadcast via mov.b64.
// ---------------------------------------------------------------------------
__global__ void __launch_bounds__(256, 2)
cmat_partial_kernel(const float* __restrict__ h1, const float* __restrict__ h2) {
    extern __shared__ float sm[];
    float* Ns = sm;             // 64 x LD
    float* Hs = sm + 64 * LD;   // 64 x LD

    const int s = blockIdx.x, b = blockIdx.y, w = blockIdx.z;
    const int tid = threadIdx.x;
    const float* Nsrc = (w == 0 ? g_n2 : g_n1) + (size_t)(b * Nn + s * RC) * H;
    const float* Hsrc = (w == 0 ? h2   : h1  ) + (size_t)(b * Nn + s * RC) * H;

    const int ty = tid >> 4, tx = tid & 15;
    const int k0 = ty * 8, h0 = tx * 8;

    unsigned long long accp[4][8];   // (C[k0+2i2][h0+j], C[k0+2i2+1][h0+j])
#pragma unroll
    for (int i = 0; i < 4; i++)
#pragma unroll
        for (int j = 0; j < 8; j++) accp[i][j] = 0ull;

    for (int stage = 0; stage < 2; ++stage) {
        __syncthreads();
        const float* Np = Nsrc + (size_t)stage * 64 * H;
        const float* Hp = Hsrc + (size_t)stage * 64 * H;
        for (int i = tid; i < 64 * (H / 4); i += 256) {
            int r = i >> 5, c4 = (i & 31) << 2;
            *(float4*)&Ns[r * LD + c4] = *(const float4*)&Np[r * H + c4];
            *(float4*)&Hs[r * LD + c4] = *(const float4*)&Hp[r * H + c4];
        }
        __syncthreads();

#pragma unroll 4
        for (int r = 0; r < 64; ++r) {
            ulonglong2 a0 = *(ulonglong2*)&Ns[r * LD + k0];
            ulonglong2 a1 = *(ulonglong2*)&Ns[r * LD + k0 + 4];
            float4 b0 = *(float4*)&Hs[r * LD + h0];
            float4 b1 = *(float4*)&Hs[r * LD + h0 + 4];
            unsigned long long au[4] = {a0.x, a0.y, a1.x, a1.y};
            unsigned long long bu[8] = {bcast2(b0.x), bcast2(b0.y), bcast2(b0.z), bcast2(b0.w),
                                        bcast2(b1.x), bcast2(b1.y), bcast2(b1.z), bcast2(b1.w)};
#pragma unroll
            for (int i = 0; i < 4; i++)
#pragma unroll
                for (int j = 0; j < 8; j++) ffma2(accp[i][j], au[i], bu[j]);
        }
    }

    float* P = g_part + ((size_t)(w * B + b) * SPL + s) * (H * H);
#pragma unroll
    for (int i2 = 0; i2 < 4; i2++) {
        float lo[8], hi[8];
#pragma unroll
        for (int j = 0; j < 8; j++) {
            float2 v = lohi(accp[i2][j]);
            lo[j] = v.x; hi[j] = v.y;
        }
        *(float4*)&P[(k0 + 2 * i2) * H + h0]         = make_float4(lo[0], lo[1], lo[2], lo[3]);
        *(float4*)&P[(k0 + 2 * i2) * H + h0 + 4]     = make_float4(lo[4], lo[5], lo[6], lo[7]);
        *(float4*)&P[(k0 + 2 * i2 + 1) * H + h0]     = make_float4(hi[0], hi[1], hi[2], hi[3]);
        *(float4*)&P[(k0 + 2 * i2 + 1) * H + h0 + 4] = make_float4(hi[4], hi[5], hi[6], hi[7]);
    }
}

// ---------------------------------------------------------------------------
// K2b: reduce SPL partials -> g_C
// ---------------------------------------------------------------------------
__global__ void cmat_reduce_kernel() {
    const int b = blockIdx.y, w = blockIdx.z;
    const int e = blockIdx.x * 256 + threadIdx.x;
    const float* P = g_part + (size_t)(w * B + b) * SPL * (H * H);
    float sum = 0.0f;
#pragma unroll
    for (int s = 0; s < SPL; s++) sum += P[(size_t)s * (H * H) + e];
    g_C[(size_t)(w * B + b) * (H * H) + e] = sum;
}

// ---------------------------------------------------------------------------
// K3: apply — agg = N · C  (64-row tiles). Packed: j-pairs of C natural,
// N broadcast via mov.b64. 2 CTAs/SM.
// ---------------------------------------------------------------------------
__global__ void __launch_bounds__(256, 2) apply_kernel() {
    extern __shared__ float sm[];
    float* Nt = sm;              // 64 x LD
    float* Cs = sm + 64 * LD;    // 128 x LD

    const int mt = blockIdx.x, b = blockIdx.y, dir = blockIdx.z;
    const int tid = threadIdx.x;
    const float* Nsrc = (dir == 0 ? g_n1 : g_n2) + (size_t)(b * Nn + mt * 64) * H;
    const float* Csrc = g_C + (size_t)(dir * B + b) * (H * H);
    float* O = (dir == 0 ? g_agg1 : g_agg2) + (size_t)(b * Nn + mt * 64) * H;

    for (int i = tid; i < 64 * (H / 4); i += 256) {
        int r = i >> 5, c4 = (i & 31) << 2;
        *(float4*)&Nt[r * LD + c4] = *(const float4*)&Nsrc[r * H + c4];
    }
    for (int i = tid; i < 128 * (H / 4); i += 256) {
        int r = i >> 5, c4 = (i & 31) << 2;
        *(float4*)&Cs[r * LD + c4] = *(const float4*)&Csrc[r * H + c4];
    }
    __syncthreads();

    const int ty = tid >> 4, tx = tid & 15;
    const int r0 = ty * 4, h0 = tx * 8;

    unsigned long long accp[4][4];   // (agg[r0+i][h0+2j2], agg[r0+i][h0+2j2+1])
#pragma unroll
    for (int i = 0; i < 4; i++)
#pragma unroll
        for (int j = 0; j < 4; j++) accp[i][j] = 0ull;

#pragma unroll 2
    for (int k4 = 0; k4 < H; k4 += 4) {
        float4 a4[4];
#pragma unroll
        for (int i = 0; i < 4; i++) a4[i] = *(float4*)&Nt[(r0 + i) * LD + k4];
#pragma unroll
        for (int kk = 0; kk < 4; kk++) {
            ulonglong2 c0v = *(ulonglong2*)&Cs[(k4 + kk) * LD + h0];
            ulonglong2 c1v = *(ulonglong2*)&Cs[(k4 + kk) * LD + h0 + 4];
            unsigned long long cu[4] = {c0v.x, c0v.y, c1v.x, c1v.y};
#pragma unroll
            for (int i = 0; i < 4; i++) {
                unsigned long long ab = bcast2((&a4[i].x)[kk]);
#pragma unroll
                for (int j = 0; j < 4; j++) ffma2(accp[i][j], ab, cu[j]);
            }
        }
    }

#pragma unroll
    for (int i = 0; i < 4; i++) {
        float v[8];
#pragma unroll
        for (int j = 0; j < 4; j++) {
            float2 p = lohi(accp[i][j]);
            v[2 * j] = p.x; v[2 * j + 1] = p.y;
        }
        *(float4*)&O[(r0 + i) * H + h0]     = make_float4(v[0], v[1], v[2], v[3]);
        *(float4*)&O[(r0 + i) * H + h0 + 4] = make_float4(v[4], v[5], v[6], v[7]);
    }
}

// ---------------------------------------------------------------------------
// K4: _fm epilogue, packed along l (even/odd partial sums, horizontal add at end).
// ---------------------------------------------------------------------------
__global__ void __launch_bounds__(256, 1)
fm_kernel(const float* __restrict__ h1, const float* __restrict__ h2,
          const float* __restrict__ w_m, float* __restrict__ out) {
    extern __shared__ float sm[];
    float* P  = sm;              // x*y   TM*LD
    float* XX = P + TM * LD;     // x*x
    float* YY = XX + TM * LD;    // y*y
    float* Ws = YY + TM * LD;    // W2 chunk (64 k-rows)

    const int tid = threadIdx.x;
    const int b = blockIdx.y, mt = blockIdx.x, dir = blockIdx.z;
    const float* X = (dir == 0 ? h1 : h2) + (size_t)(b * Nn + mt * TM) * H;
    const float* Y = (dir == 0 ? g_agg1 : g_agg2) + (size_t)(b * Nn + mt * TM) * H;
    float* Ob = out + (size_t)((dir * B + b) * Nn + mt * TM) * H;

    for (int i = tid; i < TM * (H / 4); i += 256) {
        int r = i >> 5, c4 = (i & 31) << 2;
        float4 xv = *(const float4*)&X[r * H + c4];
        float4 yv = *(const float4*)&Y[r * H + c4];
        *(float4*)&P[r * LD + c4]  = make_float4(xv.x * yv.x, xv.y * yv.y, xv.z * yv.z, xv.w * yv.w);
        *(float4*)&XX[r * LD + c4] = make_float4(xv.x * xv.x, xv.y * xv.y, xv.z * xv.z, xv.w * xv.w);
        *(float4*)&YY[r * LD + c4] = make_float4(yv.x * yv.x, yv.y * yv.y, yv.z * yv.z, yv.w * yv.w);
    }

    const int ty = tid >> 4, tx = tid & 15;
    const int r0 = ty * 4, c0 = tx * 4;

    for (int ch = 0; ch < 2; ++ch) {
        __syncthreads();
        for (int i = tid; i < TM * (H / 4); i += 256) {
            int r = i >> 5, c4 = (i & 31) << 2;
            float4 w = *(const float4*)&w_m[(size_t)(ch * TM + r) * H + c4];
            *(float4*)&Ws[r * LD + c4] =
                make_float4(w.x * w.x, w.y * w.y, w.z * w.z, w.w * w.w);
        }
        __syncthreads();

        unsigned long long an[4][4], ax[4][4], ay[4][4];
#pragma unroll
        for (int i = 0; i < 4; i++)
#pragma unroll
            for (int j = 0; j < 4; j++) { an[i][j] = 0ull; ax[i][j] = 0ull; ay[i][j] = 0ull; }

#pragma unroll 4
        for (int l = 0; l < H; l += 4) {
            ulonglong2 pv[4], xv[4], yv[4], wv[4];
#pragma unroll
            for (int i = 0; i < 4; i++) {
                pv[i] = *(ulonglong2*)&P[(r0 + i) * LD + l];
                xv[i] = *(ulonglong2*)&XX[(r0 + i) * LD + l];
                yv[i] = *(ulonglong2*)&YY[(r0 + i) * LD + l];
            }
#pragma unroll
            for (int j = 0; j < 4; j++) wv[j] = *(ulonglong2*)&Ws[(c0 + j) * LD + l];
#pragma unroll
            for (int i = 0; i < 4; i++)
#pragma unroll
                for (int j = 0; j < 4; j++) {
                    ffma2(an[i][j], pv[i].x, wv[j].x);
                    ffma2(an[i][j], pv[i].y, wv[j].y);
                    ffma2(ax[i][j], xv[i].x, wv[j].x);
                    ffma2(ax[i][j], xv[i].y, wv[j].y);
                    ffma2(ay[i][j], yv[i].x, wv[j].x);
                    ffma2(ay[i][j], yv[i].y, wv[j].y);
                }
        }

#pragma unroll
        for (int i = 0; i < 4; i++) {
            float4 o;
            float* op = &o.x;
#pragma unroll
            for (int j = 0; j < 4; j++) {
                float2 n2 = lohi(an[i][j]);
                float2 x2 = lohi(ax[i][j]);
                float2 y2 = lohi(ay[i][j]);
                float num = n2.x + n2.y;
                float dx = fmaxf(sqrtf(x2.x + x2.y), EPSF);
                float dy = fmaxf(sqrtf(y2.x + y2.y), EPSF);
                op[j] = num / (dx * dy);
            }
            *(float4*)&Ob[(r0 + i) * H + ch * TM + c0] = o;
        }
    }
}

// ---------------------------------------------------------------------------
extern "C" void kernel_launch(void* const* d_in, const int* in_sizes, int n_in,
                              void* d_out, int out_size) {
    const float* h1  = (const float*)d_in[0];
    const float* h2  = (const float*)d_in[1];
    const float* w_m = (const float*)d_in[2];
    float* out = (float*)d_out;

    constexpr int CM_SMEM = 2 * 64 * LD * (int)sizeof(float);          // 67.6 KB
    constexpr int AP_SMEM = (64 + 128) * LD * (int)sizeof(float);      // 101.4 KB
    constexpr int FM_SMEM = 4 * TM * LD * (int)sizeof(float);          // 135 KB

    cudaFuncSetAttribute(cmat_partial_kernel, cudaFuncAttributeMaxDynamicSharedMemorySize, CM_SMEM);
    cudaFuncSetAttribute(apply_kernel,        cudaFuncAttributeMaxDynamicSharedMemorySize, AP_SMEM);
    cudaFuncSetAttribute(fm_kernel,           cudaFuncAttributeMaxDynamicSharedMemorySize, FM_SMEM);

    normalize_kernel<<<(2 * B * Nn) / 8, 256>>>(h1, h2);
    cmat_partial_kernel<<<dim3(SPL, B, 2), 256, CM_SMEM>>>(h1, h2);
    cmat_reduce_kernel<<<dim3(H * H / 256, B, 2), 256>>>();
    apply_kernel<<<dim3(Nn / 64, B, 2), 256, AP_SMEM>>>();
    fm_kernel<<<dim3(Nn / TM, B, 2), 256, FM_SMEM>>>(h1, h2, w_m, out);
}

// round 6
// speedup vs baseline: 2.1867x; 2.1867x over previous
#include <cuda_runtime.h>
#include <cuda_bf16.h>
#include <cstdint>

#define EPSF 1e-8f
constexpr int B  = 8;
constexpr int Nn = 2048;
constexpr int H  = 128;
constexpr int LD = 132;         // padded smem leading dim (floats) for fp32 kernels
constexpr int SPL = 16;         // split-K factor for C = N^T H
constexpr int RC  = Nn / SPL;   // 128 rows per split

// Scratch (device globals: allocation-free rule)
__device__ float g_n1[B * Nn * H];
__device__ float g_n2[B * Nn * H];
__device__ float g_agg1[B * Nn * H];
__device__ float g_agg2[B * Nn * H];
__device__ float g_part[2 * B * SPL * H * H];
__device__ float g_C[2 * B * H * H];
// bf16 split planes for fm MMA: [2 dir][8 b][3 ch][2048][128]
__device__ __nv_bfloat16 g_fmAhi[2 * B * 3 * Nn * H];
__device__ __nv_bfloat16 g_fmAlo[2 * B * 3 * Nn * H];
__device__ __nv_bfloat16 g_w2hi[H * H];
__device__ __nv_bfloat16 g_w2lo[H * H];
// fm MMA outputs: [3 ch][2 dir][8 b][2048][128]
__device__ float g_fmD[3 * 2 * B * Nn * H];

// ======================= warp MMA helpers (base ISA, sm_80+) =================
__device__ __forceinline__ uint32_t smem_to_u32(const void* p) {
    uint32_t a;
    asm("{ .reg .u64 t; cvta.to.shared.u64 t, %1; cvt.u32.u64 %0, t; }" : "=r"(a) : "l"(p));
    return a;
}
__device__ __forceinline__ void ldsm4(uint32_t* r, uint32_t addr) {
    asm volatile("ldmatrix.sync.aligned.m8n8.x4.shared.b16 {%0,%1,%2,%3}, [%4];"
                 : "=r"(r[0]), "=r"(r[1]), "=r"(r[2]), "=r"(r[3]) : "r"(addr));
}
__device__ __forceinline__ void mma_bf16(float* c, const uint32_t* a,
                                         uint32_t b0, uint32_t b1) {
    asm volatile("mma.sync.aligned.m16n8k16.row.col.f32.bf16.bf16.f32 "
                 "{%0,%1,%2,%3}, {%4,%5,%6,%7}, {%8,%9}, {%0,%1,%2,%3};"
                 : "+f"(c[0]), "+f"(c[1]), "+f"(c[2]), "+f"(c[3])
                 : "r"(a[0]), "r"(a[1]), "r"(a[2]), "r"(a[3]), "r"(b0), "r"(b1));
}

// ---------------------------------------------------------------------------
// K1: row-normalize (round-3, unchanged)
// ---------------------------------------------------------------------------
__global__ void normalize_kernel(const float* __restrict__ h1,
                                 const float* __restrict__ h2) {
    int warp = (blockIdx.x * blockDim.x + threadIdx.x) >> 5;
    int lane = threadIdx.x & 31;
    const float* src; float* dst; int row;
    if (warp < B * Nn) { src = h1; dst = g_n1; row = warp; }
    else               { src = h2; dst = g_n2; row = warp - B * Nn; }
    float4 v = ((const float4*)(src + (size_t)row * H))[lane];
    float ss = v.x * v.x + v.y * v.y + v.z * v.z + v.w * v.w;
#pragma unroll
    for (int o = 16; o; o >>= 1) ss += __shfl_xor_sync(0xffffffffu, ss, o);
    float inv = 1.0f / fmaxf(sqrtf(ss), EPSF);
    ((float4*)(dst + (size_t)row * H))[lane] =
        make_float4(v.x * inv, v.y * inv, v.z * inv, v.w * inv);
}

// ---------------------------------------------------------------------------
// K2a: split-K partials of C = N^T H (round-3 version, unchanged)
// ---------------------------------------------------------------------------
__global__ void cmat_partial_kernel(const float* __restrict__ h1,
                                    const float* __restrict__ h2) {
    extern __shared__ float sm[];
    float* Ns = sm;
    float* Hs = sm + RC * LD;
    const int s = blockIdx.x, b = blockIdx.y, w = blockIdx.z;
    const int tid = threadIdx.x;
    const float* Nsrc = (w == 0 ? g_n2 : g_n1) + (size_t)(b * Nn + s * RC) * H;
    const float* Hsrc = (w == 0 ? h2   : h1  ) + (size_t)(b * Nn + s * RC) * H;
    for (int i = tid; i < RC * (H / 4); i += 256) {
        int r = i >> 5, c4 = (i & 31) << 2;
        *(float4*)&Ns[r * LD + c4] = *(const float4*)&Nsrc[r * H + c4];
        *(float4*)&Hs[r * LD + c4] = *(const float4*)&Hsrc[r * H + c4];
    }
    __syncthreads();
    const int ty = tid >> 4, tx = tid & 15;
    const int k0 = ty * 8, h0 = tx * 8;
    float acc[8][8];
#pragma unroll
    for (int i = 0; i < 8; i++)
#pragma unroll
        for (int j = 0; j < 8; j++) acc[i][j] = 0.0f;
#pragma unroll 4
    for (int r = 0; r < RC; ++r) {
        float a[8], bb[8];
        *(float4*)&a[0]  = *(float4*)&Ns[r * LD + k0];
        *(float4*)&a[4]  = *(float4*)&Ns[r * LD + k0 + 4];
        *(float4*)&bb[0] = *(float4*)&Hs[r * LD + h0];
        *(float4*)&bb[4] = *(float4*)&Hs[r * LD + h0 + 4];
#pragma unroll
        for (int i = 0; i < 8; i++)
#pragma unroll
            for (int j = 0; j < 8; j++) acc[i][j] += a[i] * bb[j];
    }
    float* P = g_part + ((size_t)(w * B + b) * SPL + s) * (H * H);
#pragma unroll
    for (int i = 0; i < 8; i++) {
        *(float4*)&P[(k0 + i) * H + h0]     = make_float4(acc[i][0], acc[i][1], acc[i][2], acc[i][3]);
        *(float4*)&P[(k0 + i) * H + h0 + 4] = make_float4(acc[i][4], acc[i][5], acc[i][6], acc[i][7]);
    }
}

__global__ void cmat_reduce_kernel() {
    const int b = blockIdx.y, w = blockIdx.z;
    const int e = blockIdx.x * 256 + threadIdx.x;
    const float* P = g_part + (size_t)(w * B + b) * SPL * (H * H);
    float sum = 0.0f;
#pragma unroll
    for (int s = 0; s < SPL; s++) sum += P[(size_t)s * (H * H) + e];
    g_C[(size_t)(w * B + b) * (H * H) + e] = sum;
}

// ---------------------------------------------------------------------------
// K3: apply — agg = N · C (round-3 version, unchanged)
// ---------------------------------------------------------------------------
__global__ void apply_kernel() {
    extern __shared__ float sm[];
    float* Nt = sm;
    float* Cs = sm + 128 * LD;
    const int mt = blockIdx.x, b = blockIdx.y, dir = blockIdx.z;
    const int tid = threadIdx.x;
    const float* Nsrc = (dir == 0 ? g_n1 : g_n2) + (size_t)(b * Nn + mt * 128) * H;
    const float* Csrc = g_C + (size_t)(dir * B + b) * (H * H);
    float* O = (dir == 0 ? g_agg1 : g_agg2) + (size_t)(b * Nn + mt * 128) * H;
    for (int i = tid; i < 128 * (H / 4); i += 256) {
        int r = i >> 5, c4 = (i & 31) << 2;
        *(float4*)&Nt[r * LD + c4] = *(const float4*)&Nsrc[r * H + c4];
        *(float4*)&Cs[r * LD + c4] = *(const float4*)&Csrc[r * H + c4];
    }
    __syncthreads();
    const int ty = tid >> 4, tx = tid & 15;
    const int r0 = ty * 8, h0 = tx * 8;
    float acc[8][8];
#pragma unroll
    for (int i = 0; i < 8; i++)
#pragma unroll
        for (int j = 0; j < 8; j++) acc[i][j] = 0.0f;
#pragma unroll 2
    for (int k4 = 0; k4 < H; k4 += 4) {
        float4 a4[8];
#pragma unroll
        for (int i = 0; i < 8; i++) a4[i] = *(float4*)&Nt[(r0 + i) * LD + k4];
#pragma unroll
        for (int kk = 0; kk < 4; kk++) {
            float bb[8];
            *(float4*)&bb[0] = *(float4*)&Cs[(k4 + kk) * LD + h0];
            *(float4*)&bb[4] = *(float4*)&Cs[(k4 + kk) * LD + h0 + 4];
#pragma unroll
            for (int i = 0; i < 8; i++) {
                float av = (&a4[i].x)[kk];
#pragma unroll
                for (int j = 0; j < 8; j++) acc[i][j] += av * bb[j];
            }
        }
    }
#pragma unroll
    for (int i = 0; i < 8; i++) {
        *(float4*)&O[(r0 + i) * H + h0]     = make_float4(acc[i][0], acc[i][1], acc[i][2], acc[i][3]);
        *(float4*)&O[(r0 + i) * H + h0 + 4] = make_float4(acc[i][4], acc[i][5], acc[i][6], acc[i][7]);
    }
}

// ---------------------------------------------------------------------------
// K4a: W2 = w*w, split to bf16 hi/lo
// ---------------------------------------------------------------------------
__device__ __forceinline__ uint32_t pack_bf2(float a, float b) {
    __nv_bfloat162 t = __floats2bfloat162_rn(a, b);
    return *reinterpret_cast<uint32_t*>(&t);
}
__global__ void w2_prep_kernel(const float* __restrict__ w_m) {
    int u = blockIdx.x * 256 + threadIdx.x;      // float4 unit, H*H/4 = 4096
    float4 w = *(const float4*)&w_m[u * 4];
    float v[4] = {w.x * w.x, w.y * w.y, w.z * w.z, w.w * w.w};
    float hi[4], lo[4];
#pragma unroll
    for (int i = 0; i < 4; i++) {
        __nv_bfloat16 h = __float2bfloat16(v[i]);
        hi[i] = __bfloat162float(h);
        lo[i] = v[i] - hi[i];
    }
    *(uint2*)&g_w2hi[u * 4] = make_uint2(pack_bf2(hi[0], hi[1]), pack_bf2(hi[2], hi[3]));
    *(uint2*)&g_w2lo[u * 4] = make_uint2(pack_bf2(lo[0], lo[1]), pack_bf2(lo[2], lo[3]));
}

// ---------------------------------------------------------------------------
// K4b: fm prep — p = x*y, xx = x*x, yy = y*y, split to bf16 hi/lo planes
// ---------------------------------------------------------------------------
__global__ void fm_prep_kernel(const float* __restrict__ h1,
                               const float* __restrict__ h2) {
    int u = blockIdx.x * 256 + threadIdx.x;      // float4 units: 2*8*2048*32
    int col4 = (u & 31) << 2;
    int rowg = u >> 5;
    int dir = rowg >> 14;
    int br  = rowg & 16383;                      // b*2048 + n
    int b   = br >> 11, n = br & 2047;
    const float* X = (dir ? h2 : h1) + (size_t)br * H + col4;
    const float* Y = (dir ? g_agg2 : g_agg1) + (size_t)br * H + col4;
    float4 x = *(const float4*)X;
    float4 y = *(const float4*)Y;
    float ch[3][4] = {
        {x.x * y.x, x.y * y.y, x.z * y.z, x.w * y.w},
        {x.x * x.x, x.y * x.y, x.z * x.z, x.w * x.w},
        {y.x * y.x, y.y * y.y, y.z * y.z, y.w * y.w}};
#pragma unroll
    for (int c = 0; c < 3; c++) {
        float hi[4], lo[4];
#pragma unroll
        for (int i = 0; i < 4; i++) {
            __nv_bfloat16 hh = __float2bfloat16(ch[c][i]);
            hi[i] = __bfloat162float(hh);
            lo[i] = ch[c][i] - hi[i];
        }
        size_t off = (((size_t)(dir * B + b) * 3 + c) * Nn + n) * H + col4;
        *(uint2*)&g_fmAhi[off] = make_uint2(pack_bf2(hi[0], hi[1]), pack_bf2(hi[2], hi[3]));
        *(uint2*)&g_fmAlo[off] = make_uint2(pack_bf2(lo[0], lo[1]), pack_bf2(lo[2], lo[3]));
    }
}

// ---------------------------------------------------------------------------
// K4c: fm MMA via warp mma.sync (base ISA).
// CTA: (mt, b, z) with z = dir*3 + ch. Computes D[128 rows, 128 cols] for one
// channel: D[r,k] = sum_l A[r,l] * W2[k,l], split-bf16 3-term.
// SMEM planes (272B row stride, 128 rows): Ahi@0, Alo@34816, Bhi@69632, Blo@104448.
// ---------------------------------------------------------------------------
constexpr int AROW = 272;                       // 136 bf16 per row
constexpr int PLANE = 128 * AROW;               // 34816 bytes
constexpr int FMM_SMEM = 4 * PLANE;             // 139264 bytes

__global__ void __launch_bounds__(256, 1) fm_mma_kernel() {
    extern __shared__ char smem[];
    uint32_t sb = smem_to_u32(smem);
    const int tid = threadIdx.x, wid = tid >> 5, lane = tid & 31;
    const int mt = blockIdx.x, b = blockIdx.y;
    const int dir = blockIdx.z / 3, ch = blockIdx.z % 3;

    size_t abase = (((size_t)(dir * B + b) * 3 + ch) * Nn + (size_t)mt * 128) * H;
    const __nv_bfloat16* Ahg = g_fmAhi + abase;
    const __nv_bfloat16* Alg = g_fmAlo + abase;

    for (int i = tid; i < 128 * 16; i += 256) {
        int r = i >> 4, ck = i & 15;
        uint32_t d = (uint32_t)r * AROW + (uint32_t)ck * 16;
        *(uint4*)(smem + d)             = *(const uint4*)(Ahg + r * H + ck * 8);
        *(uint4*)(smem + PLANE + d)     = *(const uint4*)(Alg + r * H + ck * 8);
        *(uint4*)(smem + 2 * PLANE + d) = *(const uint4*)(g_w2hi + r * H + ck * 8);
        *(uint4*)(smem + 3 * PLANE + d) = *(const uint4*)(g_w2lo + r * H + ck * 8);
    }
    __syncthreads();

    const int wm = (wid >> 1) * 32, wn = (wid & 1) * 64;
    const int lr = lane & 15;
    const uint32_t lc2 = (uint32_t)(lane >> 4) * 16;      // (lane/16)*8 cols * 2B
    uint32_t aoff[2], boff[4];
#pragma unroll
    for (int mi = 0; mi < 2; mi++)
        aoff[mi] = sb + (uint32_t)(wm + mi * 16 + lr) * AROW + lc2;
#pragma unroll
    for (int jp = 0; jp < 4; jp++)
        boff[jp] = sb + 2 * PLANE + (uint32_t)(wn + jp * 16 + lr) * AROW + lc2;

    float acc[2][8][4];
#pragma unroll
    for (int mi = 0; mi < 2; mi++)
#pragma unroll
        for (int j = 0; j < 8; j++)
#pragma unroll
            for (int q = 0; q < 4; q++) acc[mi][j][q] = 0.0f;

#pragma unroll 2
    for (int ks = 0; ks < 8; ks++) {
        uint32_t kb = (uint32_t)ks * 32;                  // 16 cols * 2B
        uint32_t ah[2][4], al[2][4];
#pragma unroll
        for (int mi = 0; mi < 2; mi++) {
            ldsm4(ah[mi], aoff[mi] + kb);
            ldsm4(al[mi], aoff[mi] + PLANE + kb);
        }
        uint32_t bh[4][4], bl[4][4];
#pragma unroll
        for (int jp = 0; jp < 4; jp++) {
            ldsm4(bh[jp], boff[jp] + kb);
            ldsm4(bl[jp], boff[jp] + PLANE + kb);
        }
#pragma unroll
        for (int j = 0; j < 8; j++) {
            uint32_t b0h = bh[j >> 1][j & 1], b1h = bh[j >> 1][(j & 1) + 2];
            uint32_t b0l = bl[j >> 1][j & 1], b1l = bl[j >> 1][(j & 1) + 2];
#pragma unroll
            for (int mi = 0; mi < 2; mi++) {
                mma_bf16(acc[mi][j], ah[mi], b0h, b1h);   // hi*hi
                mma_bf16(acc[mi][j], al[mi], b0h, b1h);   // lo*hi
                mma_bf16(acc[mi][j], ah[mi], b0l, b1l);   // hi*lo
            }
        }
    }

    float* D = g_fmD + (((size_t)(ch * 2 + dir) * B + b) * Nn + (size_t)mt * 128) * H;
    const int g = lane >> 2, tc = (lane & 3) * 2;
#pragma unroll
    for (int mi = 0; mi < 2; mi++)
#pragma unroll
        for (int j = 0; j < 8; j++) {
            int row = wm + mi * 16 + g, col = wn + j * 8 + tc;
            *(float2*)&D[(size_t)row * H + col]       = make_float2(acc[mi][j][0], acc[mi][j][1]);
            *(float2*)&D[(size_t)(row + 8) * H + col] = make_float2(acc[mi][j][2], acc[mi][j][3]);
        }
}

// ---------------------------------------------------------------------------
// K4d: combine — out = num / (max(sqrt(dxx),eps) * max(sqrt(dyy),eps))
// ---------------------------------------------------------------------------
__global__ void fm_combine_kernel(float* __restrict__ out) {
    constexpr size_t BNH = (size_t)B * Nn * H;
    size_t u = (size_t)blockIdx.x * 256 + threadIdx.x;   // float4 units
    size_t e = u * 4;
    int dir = (int)(e / BNH);
    size_t rem = e - (size_t)dir * BNH;
    float4 num = *(const float4*)&g_fmD[(size_t)(0 * 2 + dir) * BNH + rem];
    float4 dxx = *(const float4*)&g_fmD[(size_t)(1 * 2 + dir) * BNH + rem];
    float4 dyy = *(const float4*)&g_fmD[(size_t)(2 * 2 + dir) * BNH + rem];
    float4 o;
    o.x = num.x / (fmaxf(sqrtf(dxx.x), EPSF) * fmaxf(sqrtf(dyy.x), EPSF));
    o.y = num.y / (fmaxf(sqrtf(dxx.y), EPSF) * fmaxf(sqrtf(dyy.y), EPSF));
    o.z = num.z / (fmaxf(sqrtf(dxx.z), EPSF) * fmaxf(sqrtf(dyy.z), EPSF));
    o.w = num.w / (fmaxf(sqrtf(dxx.w), EPSF) * fmaxf(sqrtf(dyy.w), EPSF));
    *(float4*)&out[e] = o;
}

// ---------------------------------------------------------------------------
extern "C" void kernel_launch(void* const* d_in, const int* in_sizes, int n_in,
                              void* d_out, int out_size) {
    const float* h1  = (const float*)d_in[0];
    const float* h2  = (const float*)d_in[1];
    const float* w_m = (const float*)d_in[2];
    float* out = (float*)d_out;

    constexpr int CM_SMEM = 2 * RC * LD * (int)sizeof(float);       // ~135 KB
    constexpr int AP_SMEM = 2 * 128 * LD * (int)sizeof(float);      // ~135 KB

    cudaFuncSetAttribute(cmat_partial_kernel, cudaFuncAttributeMaxDynamicSharedMemorySize, CM_SMEM);
    cudaFuncSetAttribute(apply_kernel,        cudaFuncAttributeMaxDynamicSharedMemorySize, AP_SMEM);
    cudaFuncSetAttribute(fm_mma_kernel,       cudaFuncAttributeMaxDynamicSharedMemorySize, FMM_SMEM);

    normalize_kernel<<<(2 * B * Nn) / 8, 256>>>(h1, h2);
    w2_prep_kernel<<<H * H / 4 / 256, 256>>>(w_m);
    cmat_partial_kernel<<<dim3(SPL, B, 2), 256, CM_SMEM>>>(h1, h2);
    cmat_reduce_kernel<<<dim3(H * H / 256, B, 2), 256>>>();
    apply_kernel<<<dim3(Nn / 128, B, 2), 256, AP_SMEM>>>();
    fm_prep_kernel<<<2 * B * Nn * (H / 4) / 256, 256>>>(h1, h2);
    fm_mma_kernel<<<dim3(Nn / 128, B, 6), 256, FMM_SMEM>>>();
    fm_combine_kernel<<<2 * B * Nn * (H / 4) / 256, 256>>>(out);
}

// round 9
// speedup vs baseline: 2.5510x; 1.1666x over previous
#include <cuda_runtime.h>
#include <cuda_bf16.h>
#include <cstdint>

#define EPSF 1e-8f
constexpr int B  = 8;
constexpr int Nn = 2048;
constexpr int H  = 128;
constexpr int LD = 132;         // padded smem leading dim (floats) for fp32 kernels
constexpr int SPL = 16;         // split-K factor for C = N^T H
constexpr int RC  = Nn / SPL;   // 128 rows per split

// Scratch (device globals: allocation-free rule)
__device__ float g_n1[B * Nn * H];
__device__ float g_n2[B * Nn * H];
__device__ float g_agg1[B * Nn * H];
__device__ float g_agg2[B * Nn * H];
__device__ float g_part[2 * B * SPL * H * H];
// bf16 split planes of normalized n: [which][b][n][k]
__device__ __nv_bfloat16 g_nbhi[2 * B * Nn * H];
__device__ __nv_bfloat16 g_nblo[2 * B * Nn * H];
// transposed split planes of C: [w][b][h][k] = C[k][h]
__device__ __nv_bfloat16 g_Cthi[2 * B * H * H];
__device__ __nv_bfloat16 g_Ctlo[2 * B * H * H];
__device__ __nv_bfloat16 g_w2hi[H * H];
__device__ __nv_bfloat16 g_w2lo[H * H];

// ======================= warp MMA helpers (base ISA, sm_80+) =================
__device__ __forceinline__ uint32_t smem_to_u32(const void* p) {
    uint32_t a;
    asm("{ .reg .u64 t; cvta.to.shared.u64 t, %1; cvt.u32.u64 %0, t; }" : "=r"(a) : "l"(p));
    return a;
}
__device__ __forceinline__ void ldsm4(uint32_t* r, uint32_t addr) {
    asm volatile("ldmatrix.sync.aligned.m8n8.x4.shared.b16 {%0,%1,%2,%3}, [%4];"
                 : "=r"(r[0]), "=r"(r[1]), "=r"(r[2]), "=r"(r[3]) : "r"(addr));
}
__device__ __forceinline__ void mma_bf16(float* c, const uint32_t* a,
                                         uint32_t b0, uint32_t b1) {
    asm volatile("mma.sync.aligned.m16n8k16.row.col.f32.bf16.bf16.f32 "
                 "{%0,%1,%2,%3}, {%4,%5,%6,%7}, {%8,%9}, {%0,%1,%2,%3};"
                 : "+f"(c[0]), "+f"(c[1]), "+f"(c[2]), "+f"(c[3])
                 : "r"(a[0]), "r"(a[1]), "r"(a[2]), "r"(a[3]), "r"(b0), "r"(b1));
}
__device__ __forceinline__ uint32_t pack_bf2(float a, float b) {
    __nv_bfloat162 t = __floats2bfloat162_rn(a, b);
    return *reinterpret_cast<uint32_t*>(&t);
}
__device__ __forceinline__ void split4(const float* v, uint2& phi, uint2& plo) {
    float hi[4], lo[4];
#pragma unroll
    for (int i = 0; i < 4; i++) {
        __nv_bfloat16 h = __float2bfloat16(v[i]);
        hi[i] = __bfloat162float(h);
        lo[i] = v[i] - hi[i];
    }
    phi = make_uint2(pack_bf2(hi[0], hi[1]), pack_bf2(hi[2], hi[3]));
    plo = make_uint2(pack_bf2(lo[0], lo[1]), pack_bf2(lo[2], lo[3]));
}

// ---------------------------------------------------------------------------
// K1: row-normalize -> fp32 n (for cmat) + bf16 hi/lo planes (for apply MMA)
// ---------------------------------------------------------------------------
__global__ void normalize_kernel(const float* __restrict__ h1,
                                 const float* __restrict__ h2) {
    int warp = (blockIdx.x * blockDim.x + threadIdx.x) >> 5;
    int lane = threadIdx.x & 31;
    int which = (warp < B * Nn) ? 0 : 1;
    int row = warp - which * B * Nn;
    const float* src = which ? h2 : h1;
    float* dst = which ? g_n2 : g_n1;

    float4 v = ((const float4*)(src + (size_t)row * H))[lane];
    float ss = v.x * v.x + v.y * v.y + v.z * v.z + v.w * v.w;
#pragma unroll
    for (int o = 16; o; o >>= 1) ss += __shfl_xor_sync(0xffffffffu, ss, o);
    float inv = 1.0f / fmaxf(sqrtf(ss), EPSF);
    float r4[4] = {v.x * inv, v.y * inv, v.z * inv, v.w * inv};
    ((float4*)(dst + (size_t)row * H))[lane] = make_float4(r4[0], r4[1], r4[2], r4[3]);

    uint2 phi, plo;
    split4(r4, phi, plo);
    size_t off = ((size_t)which * B * Nn + row) * H + lane * 4;
    *(uint2*)&g_nbhi[off] = phi;
    *(uint2*)&g_nblo[off] = plo;
}

// ---------------------------------------------------------------------------
// K2a: split-K partials of C = N^T H (fp32)
// ---------------------------------------------------------------------------
__global__ void cmat_partial_kernel(const float* __restrict__ h1,
                                    const float* __restrict__ h2) {
    extern __shared__ float sm[];
    float* Ns = sm;
    float* Hs = sm + RC * LD;
    const int s = blockIdx.x, b = blockIdx.y, w = blockIdx.z;
    const int tid = threadIdx.x;
    const float* Nsrc = (w == 0 ? g_n2 : g_n1) + (size_t)(b * Nn + s * RC) * H;
    const float* Hsrc = (w == 0 ? h2   : h1  ) + (size_t)(b * Nn + s * RC) * H;
    for (int i = tid; i < RC * (H / 4); i += 256) {
        int r = i >> 5, c4 = (i & 31) << 2;
        *(float4*)&Ns[r * LD + c4] = *(const float4*)&Nsrc[r * H + c4];
        *(float4*)&Hs[r * LD + c4] = *(const float4*)&Hsrc[r * H + c4];
    }
    __syncthreads();
    const int ty = tid >> 4, tx = tid & 15;
    const int k0 = ty * 8, h0 = tx * 8;
    float acc[8][8];
#pragma unroll
    for (int i = 0; i < 8; i++)
#pragma unroll
        for (int j = 0; j < 8; j++) acc[i][j] = 0.0f;
#pragma unroll 4
    for (int r = 0; r < RC; ++r) {
        float a[8], bb[8];
        *(float4*)&a[0]  = *(float4*)&Ns[r * LD + k0];
        *(float4*)&a[4]  = *(float4*)&Ns[r * LD + k0 + 4];
        *(float4*)&bb[0] = *(float4*)&Hs[r * LD + h0];
        *(float4*)&bb[4] = *(float4*)&Hs[r * LD + h0 + 4];
#pragma unroll
        for (int i = 0; i < 8; i++)
#pragma unroll
            for (int j = 0; j < 8; j++) acc[i][j] += a[i] * bb[j];
    }
    float* P = g_part + ((size_t)(w * B + b) * SPL + s) * (H * H);
#pragma unroll
    for (int i = 0; i < 8; i++) {
        *(float4*)&P[(k0 + i) * H + h0]     = make_float4(acc[i][0], acc[i][1], acc[i][2], acc[i][3]);
        *(float4*)&P[(k0 + i) * H + h0 + 4] = make_float4(acc[i][4], acc[i][5], acc[i][6], acc[i][7]);
    }
}

// K2b: reduce + transpose + split to bf16 planes (Ct[h,k] = C[k,h])
__global__ void cmat_reduce_kernel() {
    const int b = blockIdx.y, w = blockIdx.z;
    const int e = blockIdx.x * 256 + threadIdx.x;   // e = k*H + h
    const float* P = g_part + (size_t)(w * B + b) * SPL * (H * H);
    float sum = 0.0f;
#pragma unroll
    for (int s = 0; s < SPL; s++) sum += P[(size_t)s * (H * H) + e];
    int k = e >> 7, hcol = e & 127;
    __nv_bfloat16 hb = __float2bfloat16(sum);
    float hif = __bfloat162float(hb);
    size_t t = (size_t)(w * B + b) * (H * H) + (size_t)hcol * H + k;
    g_Cthi[t] = hb;
    g_Ctlo[t] = __float2bfloat16(sum - hif);
}

// ---------------------------------------------------------------------------
// K3: apply via mma.sync — agg[r,h] = sum_k N[r,k] * Ct[h,k], split-bf16 3-term
// CTA: (mt, b, dir), 128 rows x 128 cols.
// ---------------------------------------------------------------------------
constexpr int AROW  = 272;                 // 136 bf16 per smem row
constexpr int PLANE = 128 * AROW;          // 34816 bytes
constexpr int APM_SMEM = 4 * PLANE;        // 139264

__global__ void __launch_bounds__(256, 1) apply_mma_kernel() {
    extern __shared__ char smem[];
    uint32_t sb = smem_to_u32(smem);
    const int tid = threadIdx.x, wid = tid >> 5, lane = tid & 31;
    const int mt = blockIdx.x, b = blockIdx.y, dir = blockIdx.z;

    size_t abase = ((size_t)dir * B * Nn + (size_t)b * Nn + (size_t)mt * 128) * H;
    const __nv_bfloat16* Ahg = g_nbhi + abase;
    const __nv_bfloat16* Alg = g_nblo + abase;
    const __nv_bfloat16* Bhg = g_Cthi + (size_t)(dir * B + b) * (H * H);
    const __nv_bfloat16* Blg = g_Ctlo + (size_t)(dir * B + b) * (H * H);

    for (int i = tid; i < 128 * 16; i += 256) {
        int r = i >> 4, ck = i & 15;
        uint32_t d = (uint32_t)r * AROW + (uint32_t)ck * 16;
        *(uint4*)(smem + d)             = *(const uint4*)(Ahg + r * H + ck * 8);
        *(uint4*)(smem + PLANE + d)     = *(const uint4*)(Alg + r * H + ck * 8);
        *(uint4*)(smem + 2 * PLANE + d) = *(const uint4*)(Bhg + r * H + ck * 8);
        *(uint4*)(smem + 3 * PLANE + d) = *(const uint4*)(Blg + r * H + ck * 8);
    }
    __syncthreads();

    const int wm = (wid >> 1) * 32, wn = (wid & 1) * 64;
    const int lr = lane & 15;
    const uint32_t lc2 = (uint32_t)(lane >> 4) * 16;
    uint32_t aoff[2], boff[4];
#pragma unroll
    for (int mi = 0; mi < 2; mi++)
        aoff[mi] = sb + (uint32_t)(wm + mi * 16 + lr) * AROW + lc2;
#pragma unroll
    for (int jp = 0; jp < 4; jp++)
        boff[jp] = sb + 2 * PLANE + (uint32_t)(wn + jp * 16 + lr) * AROW + lc2;

    float acc[2][8][4];
#pragma unroll
    for (int mi = 0; mi < 2; mi++)
#pragma unroll
        for (int j = 0; j < 8; j++)
#pragma unroll
            for (int q = 0; q < 4; q++) acc[mi][j][q] = 0.0f;

#pragma unroll 2
    for (int ks = 0; ks < 8; ks++) {
        uint32_t kb = (uint32_t)ks * 32;
        uint32_t ah[2][4], al[2][4];
#pragma unroll
        for (int mi = 0; mi < 2; mi++) {
            ldsm4(ah[mi], aoff[mi] + kb);
            ldsm4(al[mi], aoff[mi] + PLANE + kb);
        }
        uint32_t bh[4][4], bl[4][4];
#pragma unroll
        for (int jp = 0; jp < 4; jp++) {
            ldsm4(bh[jp], boff[jp] + kb);
            ldsm4(bl[jp], boff[jp] + PLANE + kb);
        }
#pragma unroll
        for (int j = 0; j < 8; j++) {
            uint32_t b0h = bh[j >> 1][j & 1], b1h = bh[j >> 1][(j & 1) + 2];
            uint32_t b0l = bl[j >> 1][j & 1], b1l = bl[j >> 1][(j & 1) + 2];
#pragma unroll
            for (int mi = 0; mi < 2; mi++) {
                mma_bf16(acc[mi][j], ah[mi], b0h, b1h);
                mma_bf16(acc[mi][j], al[mi], b0h, b1h);
                mma_bf16(acc[mi][j], ah[mi], b0l, b1l);
            }
        }
    }

    float* D = (dir == 0 ? g_agg1 : g_agg2) + ((size_t)b * Nn + (size_t)mt * 128) * H;
    const int g = lane >> 2, tc = (lane & 3) * 2;
#pragma unroll
    for (int mi = 0; mi < 2; mi++)
#pragma unroll
        for (int j = 0; j < 8; j++) {
            int row = wm + mi * 16 + g, col = wn + j * 8 + tc;
            *(float2*)&D[(size_t)row * H + col]       = make_float2(acc[mi][j][0], acc[mi][j][1]);
            *(float2*)&D[(size_t)(row + 8) * H + col] = make_float2(acc[mi][j][2], acc[mi][j][3]);
        }
}

// ---------------------------------------------------------------------------
// K4a: W2 = w*w, split to bf16 hi/lo
// ---------------------------------------------------------------------------
__global__ void w2_prep_kernel(const float* __restrict__ w_m) {
    int u = blockIdx.x * 256 + threadIdx.x;
    float4 w = *(const float4*)&w_m[u * 4];
    float v[4] = {w.x * w.x, w.y * w.y, w.z * w.z, w.w * w.w};
    uint2 phi, plo;
    split4(v, phi, plo);
    *(uint2*)&g_w2hi[u * 4] = phi;
    *(uint2*)&g_w2lo[u * 4] = plo;
}

// ---------------------------------------------------------------------------
// K4b: fused fm — per CTA (64-row tile, b, dir):
//   build split planes of {x*y, x*x, y*y} in smem, 3-channel 3-term MMA vs W2,
//   combine num/(sqrt(dxx)*sqrt(dyy)) in registers, write out.
// SMEM: 6 A planes (3ch x hi/lo, 64xAROW) + W2 hi/lo (128xAROW).
// ---------------------------------------------------------------------------
constexpr int APL      = 64 * AROW;            // 17408
constexpr int FMF_BOFF = 6 * APL;              // 104448
constexpr int FMF_SMEM = FMF_BOFF + 2 * PLANE; // 174080

__global__ void __launch_bounds__(256, 1)
fm_fused_kernel(const float* __restrict__ h1, const float* __restrict__ h2,
                float* __restrict__ out) {
    extern __shared__ char smem[];
    uint32_t sb = smem_to_u32(smem);
    const int tid = threadIdx.x, wid = tid >> 5, lane = tid & 31;
    const int mt = blockIdx.x, b = blockIdx.y, dir = blockIdx.z;

    const float* X = (dir ? h2 : h1) + ((size_t)b * Nn + (size_t)mt * 64) * H;
    const float* Y = (dir ? g_agg2 : g_agg1) + ((size_t)b * Nn + (size_t)mt * 64) * H;

    // build 3 product planes, split bf16 hi/lo
    for (int i = tid; i < 64 * 32; i += 256) {
        int r = i >> 5, c4 = (i & 31) << 2;
        float4 x = *(const float4*)&X[r * H + c4];
        float4 y = *(const float4*)&Y[r * H + c4];
        float ch[3][4] = {
            {x.x * y.x, x.y * y.y, x.z * y.z, x.w * y.w},
            {x.x * x.x, x.y * x.y, x.z * x.z, x.w * x.w},
            {y.x * y.x, y.y * y.y, y.z * y.z, y.w * y.w}};
        uint32_t d = (uint32_t)r * AROW + (uint32_t)c4 * 2;
#pragma unroll
        for (int c = 0; c < 3; c++) {
            uint2 phi, plo;
            split4(ch[c], phi, plo);
            *(uint2*)(smem + (c * 2 + 0) * APL + d) = phi;
            *(uint2*)(smem + (c * 2 + 1) * APL + d) = plo;
        }
    }
    // load W2 planes
    for (int i = tid; i < 128 * 16; i += 256) {
        int r = i >> 4, ck = i & 15;
        uint32_t d = (uint32_t)r * AROW + (uint32_t)ck * 16;
        *(uint4*)(smem + FMF_BOFF + d)         = *(const uint4*)(g_w2hi + r * H + ck * 8);
        *(uint4*)(smem + FMF_BOFF + PLANE + d) = *(const uint4*)(g_w2lo + r * H + ck * 8);
    }
    __syncthreads();

    // 8 warps: warp tile 16 rows x 64 cols. wm = (wid>>1)*16, wn = (wid&1)*64.
    const int wm = (wid >> 1) * 16, wn = (wid & 1) * 64;
    const int lr = lane & 15;
    const uint32_t lc2 = (uint32_t)(lane >> 4) * 16;
    uint32_t aoff[3][2], boff[4][2];
#pragma unroll
    for (int c = 0; c < 3; c++)
#pragma unroll
        for (int hl = 0; hl < 2; hl++)
            aoff[c][hl] = sb + (uint32_t)(c * 2 + hl) * APL + (uint32_t)(wm + lr) * AROW + lc2;
#pragma unroll
    for (int jp = 0; jp < 4; jp++)
#pragma unroll
        for (int hl = 0; hl < 2; hl++)
            boff[jp][hl] = sb + FMF_BOFF + (uint32_t)hl * PLANE +
                           (uint32_t)(wn + jp * 16 + lr) * AROW + lc2;

    float acc[3][8][4];
#pragma unroll
    for (int c = 0; c < 3; c++)
#pragma unroll
        for (int j = 0; j < 8; j++)
#pragma unroll
            for (int q = 0; q < 4; q++) acc[c][j][q] = 0.0f;

    for (int ks = 0; ks < 8; ks++) {
        uint32_t kb = (uint32_t)ks * 32;
        uint32_t ah[3][4], al[3][4];
#pragma unroll
        for (int c = 0; c < 3; c++) {
            ldsm4(ah[c], aoff[c][0] + kb);
            ldsm4(al[c], aoff[c][1] + kb);
        }
        uint32_t bh[4][4], bl[4][4];
#pragma unroll
        for (int jp = 0; jp < 4; jp++) {
            ldsm4(bh[jp], boff[jp][0] + kb);
            ldsm4(bl[jp], boff[jp][1] + kb);
        }
#pragma unroll
        for (int j = 0; j < 8; j++) {
            uint32_t b0h = bh[j >> 1][j & 1], b1h = bh[j >> 1][(j & 1) + 2];
            uint32_t b0l = bl[j >> 1][j & 1], b1l = bl[j >> 1][(j & 1) + 2];
#pragma unroll
            for (int c = 0; c < 3; c++) {
                mma_bf16(acc[c][j], ah[c], b0h, b1h);
                mma_bf16(acc[c][j], al[c], b0h, b1h);
                mma_bf16(acc[c][j], ah[c], b0l, b1l);
            }
        }
    }

    // combine in registers and store
    float* O = out + ((size_t)(dir * B + b) * Nn + (size_t)mt * 64) * H;
    const int g = lane >> 2, tc = (lane & 3) * 2;
#pragma unroll
    for (int j = 0; j < 8; j++) {
        int col = wn + j * 8 + tc;
#pragma unroll
        for (int half = 0; half < 2; half++) {
            int row = wm + half * 8 + g;
            float n0 = acc[0][j][half * 2], n1 = acc[0][j][half * 2 + 1];
            float x0 = acc[1][j][half * 2], x1 = acc[1][j][half * 2 + 1];
            float y0 = acc[2][j][half * 2], y1 = acc[2][j][half * 2 + 1];
            float2 o;
            o.x = n0 / (fmaxf(sqrtf(x0), EPSF) * fmaxf(sqrtf(y0), EPSF));
            o.y = n1 / (fmaxf(sqrtf(x1), EPSF) * fmaxf(sqrtf(y1), EPSF));
            *(float2*)&O[(size_t)row * H + col] = o;
        }
    }
}

// ---------------------------------------------------------------------------
extern "C" void kernel_launch(void* const* d_in, const int* in_sizes, int n_in,
                              void* d_out, int out_size) {
    const float* h1  = (const float*)d_in[0];
    const float* h2  = (const float*)d_in[1];
    const float* w_m = (const float*)d_in[2];
    float* out = (float*)d_out;

    constexpr int CM_SMEM = 2 * RC * LD * (int)sizeof(float);       // ~135 KB

    cudaFuncSetAttribute(cmat_partial_kernel, cudaFuncAttributeMaxDynamicSharedMemorySize, CM_SMEM);
    cudaFuncSetAttribute(apply_mma_kernel,    cudaFuncAttributeMaxDynamicSharedMemorySize, APM_SMEM);
    cudaFuncSetAttribute(fm_fused_kernel,     cudaFuncAttributeMaxDynamicSharedMemorySize, FMF_SMEM);

    normalize_kernel<<<(2 * B * Nn) / 8, 256>>>(h1, h2);
    w2_prep_kernel<<<H * H / 4 / 256, 256>>>(w_m);
    cmat_partial_kernel<<<dim3(SPL, B, 2), 256, CM_SMEM>>>(h1, h2);
    cmat_reduce_kernel<<<dim3(H * H / 256, B, 2), 256>>>();
    apply_mma_kernel<<<dim3(Nn / 128, B, 2), 256, APM_SMEM>>>();
    fm_fused_kernel<<<dim3(Nn / 64, B, 2), 256, FMF_SMEM>>>(h1, h2, out);
}